// round 4
// baseline (speedup 1.0000x reference)
#include <cuda_runtime.h>
#include <math_constants.h>

// Problem constants (fixed by the dataset): B=8, N=M=8192, 3-D points.
#define MAXB 8
#define MAXN 8192
#define MAXM 8192
#define SBLK 128            // sources per block
#define NSBLK (MAXN / SBLK) // 64 source blocks per batch

typedef unsigned long long u64;

// Static scratch (allocation-free rule).
__device__ float4       g_srcp[MAXB * MAXN];       // {x, y, z, -0.5|s|^2}
__device__ ulonglong2   g_tbr[MAXB * MAXM * 2];    // per target: [2j]={(x,x),(y,y)} [2j+1]={(z,z),(k,k)}
__device__ unsigned int g_tmin[MAXB * MAXM];       // monotonic-encoded min distance
__device__ float        g_ssum[MAXB * NSBLK];

// ---- f32x2 packed math (FFMA2/FADD2 — PTX-only on sm_103a) --------------
__device__ __forceinline__ u64 pack2(float lo, float hi) {
    u64 r; asm("mov.b64 %0,{%1,%2};" : "=l"(r) : "f"(lo), "f"(hi)); return r;
}
__device__ __forceinline__ void unpack2(u64 v, float& lo, float& hi) {
    asm("mov.b64 {%0,%1},%2;" : "=f"(lo), "=f"(hi) : "l"(v));
}
__device__ __forceinline__ u64 fma2_(u64 a, u64 b, u64 c) {
    u64 d; asm("fma.rn.f32x2 %0,%1,%2,%3;" : "=l"(d) : "l"(a), "l"(b), "l"(c)); return d;
}
__device__ __forceinline__ u64 add2_(u64 a, u64 b) {
    u64 d; asm("add.rn.f32x2 %0,%1,%2;" : "=l"(d) : "l"(a), "l"(b)); return d;
}

// ---- monotonic float<->uint encoding (atomicMin-safe for any sign) ------
__device__ __forceinline__ unsigned fenc(float f) {
    unsigned b = __float_as_uint(f);
    return (b & 0x80000000u) ? ~b : (b | 0x80000000u);
}
__device__ __forceinline__ float fdec(unsigned k) {
    return __uint_as_float((k & 0x80000000u) ? (k & 0x7fffffffu) : ~k);
}

// ---------------------------------------------------------------------------
// Kernel 1: pack sources {x,y,z,-|s|^2/2}; targets into PRE-BROADCAST f32x2
// pairs (each coord duplicated into both lanes); init tmin to encoded +inf.
// ---------------------------------------------------------------------------
__global__ void chamfer_prep(const float* __restrict__ src,
                             const float* __restrict__ tgt,
                             int BN, int BM) {
    int i = blockIdx.x * blockDim.x + threadIdx.x;
    if (i < BN) {
        float x = src[3 * i], y = src[3 * i + 1], z = src[3 * i + 2];
        float k = -0.5f * (x * x + y * y + z * z);
        g_srcp[i] = make_float4(x, y, z, k);
    }
    if (i < BM) {
        g_tmin[i] = fenc(CUDART_INF_F);
        float x = tgt[3 * i], y = tgt[3 * i + 1], z = tgt[3 * i + 2];
        float k = -0.5f * (x * x + y * y + z * z);
        ulonglong2 p0, p1;
        p0.x = pack2(x, x); p0.y = pack2(y, y);
        p1.x = pack2(z, z); p1.y = pack2(k, k);
        g_tbr[2 * i]     = p0;
        g_tbr[2 * i + 1] = p1;
    }
}

// ---------------------------------------------------------------------------
// Kernel 2: fused packed pass on e = s.t - |s|^2/2 - |t|^2/2 (= -d/2);
// min d (both directions) == max e.
// Block = 128 threads = 16 target-groups (tx) x 8 source-groups (ty).
// Thread tile: 16 sources persistent (8 packed source-pairs per coord)
// x 8 targets per 128-target chunk. Targets arrive pre-broadcast: 2 LDG.128
// per target feed FFMA2 directly (no pack MOVs). Single wave: 512 CTAs @ occ4.
// ---------------------------------------------------------------------------
__global__ void __launch_bounds__(128, 4)
chamfer_main(int N, int M) {
    const int b    = blockIdx.y;
    const int sblk = blockIdx.x;
    const int tid  = threadIdx.x;
    const int tx   = tid >> 3;    // target group 0..15
    const int ty   = tid & 7;     // source-lane 0..7 (consecutive)

    const float4*     __restrict__ S = g_srcp + b * N + sblk * SBLK;
    const ulonglong2* __restrict__ T = g_tbr + (size_t)(b * M) * 2;

    // 16 persistent sources as 8 packed pairs per coordinate.
    u64 sx2[8], sy2[8], sz2[8], sk2[8];
    float smax[16];
#pragma unroll
    for (int i = 0; i < 8; i++) {
        float4 v0 = S[ty * 16 + 2 * i];
        float4 v1 = S[ty * 16 + 2 * i + 1];
        sx2[i] = pack2(v0.x, v1.x);
        sy2[i] = pack2(v0.y, v1.y);
        sz2[i] = pack2(v0.z, v1.z);
        sk2[i] = pack2(v0.w, v1.w);
        smax[2 * i] = -CUDART_INF_F;
        smax[2 * i + 1] = -CUDART_INF_F;
    }

    for (int c = 0; c < M; c += 128) {
        const int base = c + tx * 8;   // this thread's 8 targets this chunk
        float tmax[8];

        // One-deep software pipeline over targets.
        ulonglong2 p0 = T[2 * base];
        ulonglong2 p1 = T[2 * base + 1];

#pragma unroll
        for (int j = 0; j < 8; j++) {
            ulonglong2 n0, n1;
            if (j < 7) { n0 = T[2 * (base + j + 1)]; n1 = T[2 * (base + j + 1) + 1]; }

            const u64 tx2 = p0.x, ty2 = p0.y, tz2 = p1.x, tk2 = p1.y;
            float tm = -CUDART_INF_F;
#pragma unroll
            for (int i = 0; i < 8; i++) {
                u64 e2 = fma2_(sx2[i], tx2,
                         fma2_(sy2[i], ty2,
                         fma2_(sz2[i], tz2, add2_(sk2[i], tk2))));
                float elo, ehi;
                unpack2(e2, elo, ehi);   // register-pair alias: no real MOVs
                smax[2 * i]     = fmaxf(smax[2 * i], elo);
                smax[2 * i + 1] = fmaxf(smax[2 * i + 1], ehi);
                tm = fmaxf(tm, fmaxf(elo, ehi));
            }
            tmax[j] = tm;
            p0 = n0; p1 = n1;
        }

        // Array-folding butterfly: reduce tmax[8] across the 8 ty-lanes.
        // After 3 steps lane ty owns target bitrev3(ty); 7 SHFL total.
        int own = 0;
        int len = 8;
#pragma unroll
        for (int s = 1; s <= 4; s <<= 1) {
            len >>= 1;
            const bool bit = (ty & s) != 0;
#pragma unroll
            for (int k = 0; k < 4; k++) {
                if (k < len) {
                    float send = bit ? tmax[k] : tmax[k + len];
                    float keep = bit ? tmax[k + len] : tmax[k];
                    float recv = __shfl_xor_sync(0xffffffffu, send, s, 8);
                    tmax[k] = fmaxf(keep, recv);
                }
            }
            if (bit) own += len;
        }
        atomicMin(&g_tmin[b * M + base + own], fenc(-2.0f * tmax[0]));
    }

    // Finalize source mins: d_i = -2*smax_i, min across 16 tx slices, sum.
    __shared__ float red[16][136];
#pragma unroll
    for (int i = 0; i < 16; i++) red[tx][ty * 16 + i] = -2.0f * smax[i];
    __syncthreads();

    float m = red[0][tid];
#pragma unroll
    for (int k = 1; k < 16; k++) m = fminf(m, red[k][tid]);

    __shared__ float partial[128];
    partial[tid] = m;
    __syncthreads();
    if (tid < 64) partial[tid] += partial[tid + 64];
    __syncthreads();
    if (tid < 32) {
        float v = partial[tid] + partial[tid + 32];
#pragma unroll
        for (int o = 16; o > 0; o >>= 1)
            v += __shfl_down_sync(0xffffffffu, v, o);
        if (tid == 0) g_ssum[b * gridDim.x + sblk] = v;  // deterministic
    }
}

// ---------------------------------------------------------------------------
// Kernel 3: deterministic final reduction. One block per batch.
// ---------------------------------------------------------------------------
__global__ void chamfer_finish(float* __restrict__ out, int N, int M, int nsblk) {
    const int b   = blockIdx.x;
    const int tid = threadIdx.x;  // 256 threads

    float ts = 0.0f;
    for (int i = tid; i < M; i += 256)
        ts += fdec(g_tmin[b * M + i]);
    float ss = 0.0f;
    for (int i = tid; i < nsblk; i += 256)
        ss += g_ssum[b * nsblk + i];

    __shared__ float s1[256], s2[256];
    s1[tid] = ts; s2[tid] = ss;
    __syncthreads();
    for (int o = 128; o > 0; o >>= 1) {
        if (tid < o) { s1[tid] += s1[tid + o]; s2[tid] += s2[tid + o]; }
        __syncthreads();
    }
    if (tid == 0) out[b] = s1[0] / (float)M + s2[0] / (float)N;
}

// ---------------------------------------------------------------------------
extern "C" void kernel_launch(void* const* d_in, const int* in_sizes, int n_in,
                              void* d_out, int out_size) {
    const float* src = (const float*)d_in[0];
    const float* tgt = (const float*)d_in[1];
    float* out = (float*)d_out;

    const int B = out_size;                 // 8
    const int N = in_sizes[0] / (3 * B);    // 8192
    const int M = in_sizes[1] / (3 * B);    // 8192
    const int BN = B * N, BM = B * M;
    const int total = BN > BM ? BN : BM;

    chamfer_prep<<<(total + 255) / 256, 256>>>(src, tgt, BN, BM);

    dim3 grid(N / SBLK, B);
    chamfer_main<<<grid, 128>>>(N, M);

    chamfer_finish<<<B, 256>>>(out, N, M, N / SBLK);
}

// round 5
// speedup vs baseline: 1.3090x; 1.3090x over previous
#include <cuda_runtime.h>
#include <math_constants.h>

// Problem constants (fixed by the dataset): B=8, N=M=8192, 3-D points.
#define MAXB 8
#define MAXN 8192
#define MAXM 8192
#define SBLK 128            // sources per block
#define NSBLK (MAXN / SBLK) // 64 source blocks per batch

typedef unsigned long long u64;

// Static scratch (allocation-free rule).
__device__ float4       g_tpack[MAXB * MAXM];   // {x, y, z, -0.5|t|^2}
__device__ unsigned int g_tmax[MAXB * MAXM];    // encoded max-e per target
__device__ float        g_ssum[MAXB * NSBLK];   // per-block sum of max-e per source

// ---- f32x2 packed math (FFMA2/FADD2 — PTX-only on sm_103a) --------------
__device__ __forceinline__ u64 pack2(float lo, float hi) {
    u64 r; asm("mov.b64 %0,{%1,%2};" : "=l"(r) : "f"(lo), "f"(hi)); return r;
}
__device__ __forceinline__ void unpack2(u64 v, float& lo, float& hi) {
    asm("mov.b64 {%0,%1},%2;" : "=f"(lo), "=f"(hi) : "l"(v));
}
__device__ __forceinline__ u64 fma2_(u64 a, u64 b, u64 c) {
    u64 d; asm("fma.rn.f32x2 %0,%1,%2,%3;" : "=l"(d) : "l"(a), "l"(b), "l"(c)); return d;
}
__device__ __forceinline__ u64 add2_(u64 a, u64 b) {
    u64 d; asm("add.rn.f32x2 %0,%1,%2;" : "=l"(d) : "l"(a), "l"(b)); return d;
}

// ---- monotonic float<->uint encoding (order-preserving, any sign) -------
__device__ __forceinline__ unsigned fenc(float f) {
    unsigned b = __float_as_uint(f);
    return (b & 0x80000000u) ? ~b : (b | 0x80000000u);
}
__device__ __forceinline__ float fdec(unsigned k) {
    return __uint_as_float((k & 0x80000000u) ? (k & 0x7fffffffu) : ~k);
}

// ---------------------------------------------------------------------------
// Kernel 1: pack targets {x,y,z,-|t|^2/2}; init tmax to encoded -inf.
// ---------------------------------------------------------------------------
__global__ void chamfer_prep(const float* __restrict__ tgt, int BM) {
    int i = blockIdx.x * blockDim.x + threadIdx.x;
    if (i < BM) {
        float x = tgt[3 * i], y = tgt[3 * i + 1], z = tgt[3 * i + 2];
        float k = -0.5f * (x * x + y * y + z * z);
        g_tpack[i] = make_float4(x, y, z, k);
        g_tmax[i]  = fenc(-CUDART_INF_F);
    }
}

// ---------------------------------------------------------------------------
// Kernel 2: fused packed pass on e = s.t - |s|^2/2 - |t|^2/2 (= -d/2);
// min d (both directions) == max e.
// Block = 128 threads = 16 target-groups (tx) x 8 source-lanes (ty).
// 16 persistent sources/thread (8 packed pairs per coord) x 8 targets/chunk.
// Targets staged to smem via cp.async (double buffer, 1 chunk lookahead);
// inner reads are conflict-free XOR-swizzled LDS.128. Single wave: 512 CTAs.
// ---------------------------------------------------------------------------
__global__ void __launch_bounds__(128, 4)
chamfer_main(const float* __restrict__ src, int N, int M) {
    const int b    = blockIdx.y;
    const int sblk = blockIdx.x;
    const int tid  = threadIdx.x;
    const int tx   = tid >> 3;    // target group 0..15
    const int ty   = tid & 7;     // source lane 0..7 (consecutive)

    __shared__ float4 stg[2][128];

    // --- load 16 raw sources, pack into 8 f32x2 pairs per coordinate ------
    const float* __restrict__ Sp = src + ((size_t)b * N + sblk * SBLK + ty * 16) * 3;
    u64 sx2[8], sy2[8], sz2[8], sk2[8];
    float emax[16];
#pragma unroll
    for (int i = 0; i < 8; i++) {
        float x0 = Sp[6 * i],     y0 = Sp[6 * i + 1], z0 = Sp[6 * i + 2];
        float x1 = Sp[6 * i + 3], y1 = Sp[6 * i + 4], z1 = Sp[6 * i + 5];
        float k0 = -0.5f * (x0 * x0 + y0 * y0 + z0 * z0);
        float k1 = -0.5f * (x1 * x1 + y1 * y1 + z1 * z1);
        sx2[i] = pack2(x0, x1);
        sy2[i] = pack2(y0, y1);
        sz2[i] = pack2(z0, z1);
        sk2[i] = pack2(k0, k1);
        emax[2 * i]     = -CUDART_INF_F;
        emax[2 * i + 1] = -CUDART_INF_F;
    }

    const float4* __restrict__ T = g_tpack + (size_t)b * M;

    // Swizzle: physical 16B slot = t ^ ((t>>3)&3) -> the 4 tx-quadrants of a
    // warp land in distinct 32B bank groups; 8 ty-lanes broadcast.
    const int wslot = tid ^ ((tid >> 3) & 3);          // staging dst slot
    int rs[8];                                          // reader slots (chunk-invariant)
#pragma unroll
    for (int j = 0; j < 8; j++) rs[j] = tx * 8 + (j ^ (tx & 3));

    // Prologue: stage chunk 0.
    {
        unsigned dst = (unsigned)__cvta_generic_to_shared(&stg[0][wslot]);
        const float4* g = T + tid;
        asm volatile("cp.async.cg.shared.global [%0], [%1], 16;" :: "r"(dst), "l"(g));
        asm volatile("cp.async.commit_group;");
    }

    for (int c = 0; c < M; c += 128) {
        const int buf = (c >> 7) & 1;

        // Prefetch next chunk into the other buffer (safe: it was last read
        // two iterations ago, with a barrier since).
        if (c + 128 < M) {
            unsigned dst = (unsigned)__cvta_generic_to_shared(&stg[buf ^ 1][wslot]);
            const float4* g = T + c + 128 + tid;
            asm volatile("cp.async.cg.shared.global [%0], [%1], 16;" :: "r"(dst), "l"(g));
            asm volatile("cp.async.commit_group;");
            asm volatile("cp.async.wait_group 1;");
        } else {
            asm volatile("cp.async.wait_group 0;");
        }
        __syncthreads();  // current buffer visible to all threads

        float tmax[8];
#pragma unroll
        for (int j = 0; j < 8; j++) {
            float4 tv = stg[buf][rs[j]];               // LDS.128, conflict-free
            u64 tx2 = pack2(tv.x, tv.x);
            u64 ty2 = pack2(tv.y, tv.y);
            u64 tz2 = pack2(tv.z, tv.z);
            u64 tk2 = pack2(tv.w, tv.w);
            float tm = -CUDART_INF_F;
#pragma unroll
            for (int i = 0; i < 8; i++) {
                u64 e2 = fma2_(sx2[i], tx2,
                         fma2_(sy2[i], ty2,
                         fma2_(sz2[i], tz2, add2_(sk2[i], tk2))));
                float elo, ehi;
                unpack2(e2, elo, ehi);
                emax[2 * i]     = fmaxf(emax[2 * i], elo);
                emax[2 * i + 1] = fmaxf(emax[2 * i + 1], ehi);
                tm = fmaxf(tm, fmaxf(elo, ehi));
            }
            tmax[j] = tm;
        }
        __syncthreads();  // all reads of stg[buf] done before it is re-staged

        // Array-folding butterfly over the 8 ty-lanes: 7 SHFL total; after 3
        // steps lane ty owns target bitrev3(ty) and flushes it.
        int own = 0, len = 8;
#pragma unroll
        for (int s = 1; s <= 4; s <<= 1) {
            len >>= 1;
            const bool bit = (ty & s) != 0;
#pragma unroll
            for (int k = 0; k < 4; k++) {
                if (k < len) {
                    float send = bit ? tmax[k] : tmax[k + len];
                    float keep = bit ? tmax[k + len] : tmax[k];
                    float recv = __shfl_xor_sync(0xffffffffu, send, s, 8);
                    tmax[k] = fmaxf(keep, recv);
                }
            }
            if (bit) own += len;
        }
        atomicMax(&g_tmax[(size_t)b * M + c + tx * 8 + own], fenc(tmax[0]));
    }

    // Finalize source side: max-e across 16 tx slices, then block sum (e-domain).
    __shared__ float red[16][136];
#pragma unroll
    for (int i = 0; i < 16; i++) red[tx][ty * 16 + i] = emax[i];
    __syncthreads();

    float m = red[0][tid];
#pragma unroll
    for (int k = 1; k < 16; k++) m = fmaxf(m, red[k][tid]);

    __shared__ float partial[128];
    partial[tid] = m;
    __syncthreads();
    if (tid < 64) partial[tid] += partial[tid + 64];
    __syncthreads();
    if (tid < 32) {
        float v = partial[tid] + partial[tid + 32];
#pragma unroll
        for (int o = 16; o > 0; o >>= 1)
            v += __shfl_down_sync(0xffffffffu, v, o);
        if (tid == 0) g_ssum[b * gridDim.x + sblk] = v;  // deterministic
    }
}

// ---------------------------------------------------------------------------
// Kernel 3: deterministic final reduction; converts e-domain to distances.
// out[b] = mean_t(-2*emax_t) + mean_s(-2*emax_s)
// ---------------------------------------------------------------------------
__global__ void chamfer_finish(float* __restrict__ out, int N, int M, int nsblk) {
    const int b   = blockIdx.x;
    const int tid = threadIdx.x;  // 256 threads

    float ts = 0.0f;
    for (int i = tid; i < M; i += 256)
        ts += fdec(g_tmax[(size_t)b * M + i]);
    float ss = 0.0f;
    for (int i = tid; i < nsblk; i += 256)
        ss += g_ssum[b * nsblk + i];

    __shared__ float s1[256], s2[256];
    s1[tid] = ts; s2[tid] = ss;
    __syncthreads();
    for (int o = 128; o > 0; o >>= 1) {
        if (tid < o) { s1[tid] += s1[tid + o]; s2[tid] += s2[tid + o]; }
        __syncthreads();
    }
    if (tid == 0) out[b] = -2.0f * (s1[0] / (float)M + s2[0] / (float)N);
}

// ---------------------------------------------------------------------------
extern "C" void kernel_launch(void* const* d_in, const int* in_sizes, int n_in,
                              void* d_out, int out_size) {
    const float* src = (const float*)d_in[0];
    const float* tgt = (const float*)d_in[1];
    float* out = (float*)d_out;

    const int B = out_size;                 // 8
    const int N = in_sizes[0] / (3 * B);    // 8192
    const int M = in_sizes[1] / (3 * B);    // 8192
    const int BM = B * M;

    chamfer_prep<<<(BM + 255) / 256, 256>>>(tgt, BM);

    dim3 grid(N / SBLK, B);
    chamfer_main<<<grid, 128>>>(src, N, M);

    chamfer_finish<<<B, 256>>>(out, N, M, N / SBLK);
}

// round 6
// speedup vs baseline: 1.4508x; 1.1083x over previous
#include <cuda_runtime.h>
#include <math_constants.h>

// Problem constants (fixed by dataset): B=8, N=M=8192, 3-D points.
#define MAXB 8
#define MAXN 8192
#define MAXM 8192
#define CPB   74          // CTAs per batch (74*8 = 592 = 148 SMs * occ 4: one balanced wave)
#define SRCT  112         // sources per CTA tile (74*112 >= 8192, last CTA padded by clamping)
#define NPP   7           // packed source-pairs per thread (14 sources / thread)

typedef unsigned long long u64;

// Static scratch (allocation-free rule).
__device__ float4       g_tpack[MAXB * MAXM];   // {x, y, z, -0.5|t|^2}
__device__ unsigned int g_tmax[MAXB * MAXM];    // encoded max-e per target
__device__ float        g_ssum[MAXB * CPB];     // per-CTA masked sum of source max-e

// ---- f32x2 packed math (FFMA2/FADD2 — PTX-only on sm_103a) --------------
__device__ __forceinline__ u64 pack2(float lo, float hi) {
    u64 r; asm("mov.b64 %0,{%1,%2};" : "=l"(r) : "f"(lo), "f"(hi)); return r;
}
__device__ __forceinline__ void unpack2(u64 v, float& lo, float& hi) {
    asm("mov.b64 {%0,%1},%2;" : "=f"(lo), "=f"(hi) : "l"(v));
}
__device__ __forceinline__ u64 fma2_(u64 a, u64 b, u64 c) {
    u64 d; asm("fma.rn.f32x2 %0,%1,%2,%3;" : "=l"(d) : "l"(a), "l"(b), "l"(c)); return d;
}
__device__ __forceinline__ u64 add2_(u64 a, u64 b) {
    u64 d; asm("add.rn.f32x2 %0,%1,%2;" : "=l"(d) : "l"(a), "l"(b)); return d;
}

// ---- monotonic float<->uint encoding (order-preserving, any sign) -------
__device__ __forceinline__ unsigned fenc(float f) {
    unsigned b = __float_as_uint(f);
    return (b & 0x80000000u) ? ~b : (b | 0x80000000u);
}
__device__ __forceinline__ float fdec(unsigned k) {
    return __uint_as_float((k & 0x80000000u) ? (k & 0x7fffffffu) : ~k);
}

// ---------------------------------------------------------------------------
// Kernel 1: pack targets {x,y,z,-|t|^2/2}; init tmax to encoded -inf.
// ---------------------------------------------------------------------------
__global__ void chamfer_prep(const float* __restrict__ tgt, int BM) {
    int i = blockIdx.x * blockDim.x + threadIdx.x;
    if (i < BM) {
        float x = tgt[3 * i], y = tgt[3 * i + 1], z = tgt[3 * i + 2];
        float k = -0.5f * (x * x + y * y + z * z);
        g_tpack[i] = make_float4(x, y, z, k);
        g_tmax[i]  = fenc(-CUDART_INF_F);
    }
}

// ---------------------------------------------------------------------------
// Kernel 2: fused packed pass on e = s.t - |s|^2/2 - |t|^2/2 (= -d/2);
// min d (both directions) == max e.
// Grid (74, 8) = 592 CTAs = 148 SMs x occ 4: one perfectly balanced wave.
// Block = 128 threads = 16 target-groups (tx) x 8 source-lanes (ty).
// Thread: 14 persistent sources (7 packed f32x2 pairs/coord; padded CTAs clamp
// indices -> duplicates, idempotent under max) x 8 targets per 128-chunk.
// Targets staged via cp.async double buffer; swizzled conflict-free LDS.128.
// ---------------------------------------------------------------------------
__global__ void __launch_bounds__(128, 4)
chamfer_main(const float* __restrict__ src, int N, int M) {
    const int b    = blockIdx.y;
    const int sblk = blockIdx.x;
    const int tid  = threadIdx.x;
    const int tx   = tid >> 3;    // target group 0..15
    const int ty   = tid & 7;     // source lane 0..7 (consecutive)

    __shared__ float4 stg[2][128];

    // --- load 14 sources (indices clamped to batch end), pack 7 pairs -----
    const int sofs = sblk * SRCT + ty * (2 * NPP);   // within-batch offset
    const float* __restrict__ Sb = src + (size_t)b * N * 3;
    u64 sx2[NPP], sy2[NPP], sz2[NPP], sk2[NPP];
    float emax[2 * NPP];
#pragma unroll
    for (int i = 0; i < NPP; i++) {
        int i0 = min(sofs + 2 * i,     N - 1);
        int i1 = min(sofs + 2 * i + 1, N - 1);
        float x0 = Sb[3 * i0], y0 = Sb[3 * i0 + 1], z0 = Sb[3 * i0 + 2];
        float x1 = Sb[3 * i1], y1 = Sb[3 * i1 + 1], z1 = Sb[3 * i1 + 2];
        float k0 = -0.5f * (x0 * x0 + y0 * y0 + z0 * z0);
        float k1 = -0.5f * (x1 * x1 + y1 * y1 + z1 * z1);
        sx2[i] = pack2(x0, x1);
        sy2[i] = pack2(y0, y1);
        sz2[i] = pack2(z0, z1);
        sk2[i] = pack2(k0, k1);
        emax[2 * i]     = -CUDART_INF_F;
        emax[2 * i + 1] = -CUDART_INF_F;
    }

    const float4* __restrict__ T = g_tpack + (size_t)b * M;

    // Swizzle: slot = t ^ ((t>>3)&3) -> 4 tx-quadrants hit distinct 32B bank
    // groups; 8 ty-lanes broadcast.
    const int wslot = tid ^ ((tid >> 3) & 3);
    int rs[8];
#pragma unroll
    for (int j = 0; j < 8; j++) rs[j] = tx * 8 + (j ^ (tx & 3));

    // Prologue: stage chunk 0.
    {
        unsigned dst = (unsigned)__cvta_generic_to_shared(&stg[0][wslot]);
        const float4* g = T + tid;
        asm volatile("cp.async.cg.shared.global [%0], [%1], 16;" :: "r"(dst), "l"(g));
        asm volatile("cp.async.commit_group;");
    }

    for (int c = 0; c < M; c += 128) {
        const int buf = (c >> 7) & 1;

        if (c + 128 < M) {
            unsigned dst = (unsigned)__cvta_generic_to_shared(&stg[buf ^ 1][wslot]);
            const float4* g = T + c + 128 + tid;
            asm volatile("cp.async.cg.shared.global [%0], [%1], 16;" :: "r"(dst), "l"(g));
            asm volatile("cp.async.commit_group;");
            asm volatile("cp.async.wait_group 1;");
        } else {
            asm volatile("cp.async.wait_group 0;");
        }
        __syncthreads();

        float tmax[8];
#pragma unroll
        for (int j = 0; j < 8; j++) {
            float4 tv = stg[buf][rs[j]];               // LDS.128, conflict-free
            u64 tx2 = pack2(tv.x, tv.x);
            u64 ty2 = pack2(tv.y, tv.y);
            u64 tz2 = pack2(tv.z, tv.z);
            u64 tk2 = pack2(tv.w, tv.w);
            float tm = -CUDART_INF_F;
#pragma unroll
            for (int i = 0; i < NPP; i++) {
                u64 e2 = fma2_(sx2[i], tx2,
                         fma2_(sy2[i], ty2,
                         fma2_(sz2[i], tz2, add2_(sk2[i], tk2))));
                float elo, ehi;
                unpack2(e2, elo, ehi);
                emax[2 * i]     = fmaxf(emax[2 * i], elo);
                emax[2 * i + 1] = fmaxf(emax[2 * i + 1], ehi);
                tm = fmaxf(tm, fmaxf(elo, ehi));
            }
            tmax[j] = tm;
        }
        __syncthreads();

        // Array-folding butterfly over the 8 ty-lanes (7 SHFL); lane ty ends
        // owning target bitrev3(ty) and flushes it with one spread atomic.
        int own = 0, len = 8;
#pragma unroll
        for (int s = 1; s <= 4; s <<= 1) {
            len >>= 1;
            const bool bit = (ty & s) != 0;
#pragma unroll
            for (int k = 0; k < 4; k++) {
                if (k < len) {
                    float send = bit ? tmax[k] : tmax[k + len];
                    float keep = bit ? tmax[k + len] : tmax[k];
                    float recv = __shfl_xor_sync(0xffffffffu, send, s, 8);
                    tmax[k] = fmaxf(keep, recv);
                }
            }
            if (bit) own += len;
        }
        atomicMax(&g_tmax[(size_t)b * M + c + tx * 8 + own], fenc(tmax[0]));
    }

    // Source side: max-e across the 16 tx slices, mask out padded lanes, sum.
    __shared__ float red[16][120];   // 112 used, padded stride
#pragma unroll
    for (int i = 0; i < 2 * NPP; i++) red[tx][ty * (2 * NPP) + i] = emax[i];
    __syncthreads();

    float contrib = 0.0f;
    if (tid < SRCT) {
        float m = red[0][tid];
#pragma unroll
        for (int k = 1; k < 16; k++) m = fmaxf(m, red[k][tid]);
        if (sblk * SRCT + tid < N) contrib = m;   // mask padded sources
    }

    __shared__ float partial[128];
    partial[tid] = contrib;
    __syncthreads();
    if (tid < 64) partial[tid] += partial[tid + 64];
    __syncthreads();
    if (tid < 32) {
        float v = partial[tid] + partial[tid + 32];
#pragma unroll
        for (int o = 16; o > 0; o >>= 1)
            v += __shfl_down_sync(0xffffffffu, v, o);
        if (tid == 0) g_ssum[b * gridDim.x + sblk] = v;  // deterministic
    }
}

// ---------------------------------------------------------------------------
// Kernel 3: deterministic final reduction; converts e-domain to distances.
// out[b] = mean_t(-2*emax_t) + mean_s(-2*emax_s)
// ---------------------------------------------------------------------------
__global__ void chamfer_finish(float* __restrict__ out, int N, int M, int nsblk) {
    const int b   = blockIdx.x;
    const int tid = threadIdx.x;  // 256 threads

    float ts = 0.0f;
    for (int i = tid; i < M; i += 256)
        ts += fdec(g_tmax[(size_t)b * M + i]);
    float ss = 0.0f;
    for (int i = tid; i < nsblk; i += 256)
        ss += g_ssum[b * nsblk + i];

    __shared__ float s1[256], s2[256];
    s1[tid] = ts; s2[tid] = ss;
    __syncthreads();
    for (int o = 128; o > 0; o >>= 1) {
        if (tid < o) { s1[tid] += s1[tid + o]; s2[tid] += s2[tid + o]; }
        __syncthreads();
    }
    if (tid == 0) out[b] = -2.0f * (s1[0] / (float)M + s2[0] / (float)N);
}

// ---------------------------------------------------------------------------
extern "C" void kernel_launch(void* const* d_in, const int* in_sizes, int n_in,
                              void* d_out, int out_size) {
    const float* src = (const float*)d_in[0];
    const float* tgt = (const float*)d_in[1];
    float* out = (float*)d_out;

    const int B = out_size;                 // 8
    const int N = in_sizes[0] / (3 * B);    // 8192
    const int M = in_sizes[1] / (3 * B);    // 8192
    const int BM = B * M;

    chamfer_prep<<<(BM + 255) / 256, 256>>>(tgt, BM);

    dim3 grid(CPB, B);                      // 592 CTAs: one balanced wave
    chamfer_main<<<grid, 128>>>(src, N, M);

    chamfer_finish<<<B, 256>>>(out, N, M, CPB);
}